// round 14
// baseline (speedup 1.0000x reference)
#include <cuda_runtime.h>
#include <cuda_bf16.h>
#include <math.h>
#include <stdint.h>

// Problem constants
#define NB 8
#define NQ 8
#define HID 4096
#define NH 32
#define NKVH 8
#define NG 4
#define DH 128
#define LKV 4096
#define NSPLIT 16
#define MR 64                    // B*Q rows
#define SPLIT_LEN (LKV / NSPLIT) // 256
#define CS 32                    // keys per chunk
#define NCH (SPLIT_LEN / CS)     // 8
#define KSPLIT 4                 // GEMM k-split (256 blocks -> single wave)
#define KSLICE (HID / KSPLIT)    // 1024
#define NIT (KSLICE / 32)        // 32 k-iterations per block

// Scratch (device globals — no allocation allowed)
__device__ float g_part[KSPLIT * MR * HID];             // GEMM split-K partials (4MB)
__device__ float g_q[MR * HID];                         // roped+scaled Q, [bk][r][d]
__device__ float g_attn[MR * HID];                      // merged attn out [(b,qq)][h*128+d]
__device__ float g_po[NB * NKVH * NSPLIT * 32 * DH];    // partial O (unnormalized)
__device__ float g_pm[NB * NKVH * NSPLIT * 32];
__device__ float g_pl[NB * NKVH * NSPLIT * 32];
__device__ float g_cos[NB * 64];
__device__ float g_sin[NB * 64];

// ---------------------------------------------------------------------------
// FAST bf16 hi/lo split (packed cvt) + fp16 single cvt + mma helpers
// ---------------------------------------------------------------------------
__device__ __forceinline__ void split2(float x, float y, uint32_t& hi, uint32_t& lo) {
    asm("cvt.rn.bf16x2.f32 %0, %1, %2;" : "=r"(hi) : "f"(y), "f"(x));
    float hx = __uint_as_float(hi << 16);           // bf16(x) as float
    float hy = __uint_as_float(hi & 0xFFFF0000u);   // bf16(y) as float
    float lx = x - hx, ly = y - hy;
    asm("cvt.rn.bf16x2.f32 %0, %1, %2;" : "=r"(lo) : "f"(ly), "f"(lx));
}

__device__ __forceinline__ uint32_t cvt_f16x2(float x, float y) {
    uint32_t r;
    asm("cvt.rn.f16x2.f32 %0, %1, %2;" : "=r"(r) : "f"(y), "f"(x));  // x in low half
    return r;
}

__device__ __forceinline__ void mma_bf16(float c[4],
                                         uint32_t a0, uint32_t a1, uint32_t a2, uint32_t a3,
                                         uint32_t b0, uint32_t b1) {
    asm volatile(
        "mma.sync.aligned.m16n8k16.row.col.f32.bf16.bf16.f32 "
        "{%0,%1,%2,%3}, {%4,%5,%6,%7}, {%8,%9}, {%0,%1,%2,%3};\n"
        : "+f"(c[0]), "+f"(c[1]), "+f"(c[2]), "+f"(c[3])
        : "r"(a0), "r"(a1), "r"(a2), "r"(a3), "r"(b0), "r"(b1));
}

__device__ __forceinline__ void mma_f16(float c[4],
                                        uint32_t a0, uint32_t a1, uint32_t a2, uint32_t a3,
                                        uint32_t b0, uint32_t b1) {
    asm volatile(
        "mma.sync.aligned.m16n8k16.row.col.f32.f16.f16.f32 "
        "{%0,%1,%2,%3}, {%4,%5,%6,%7}, {%8,%9}, {%0,%1,%2,%3};\n"
        : "+f"(c[0]), "+f"(c[1]), "+f"(c[2]), "+f"(c[3])
        : "r"(a0), "r"(a1), "r"(a2), "r"(a3), "r"(b0), "r"(b1));
}

// ---------------------------------------------------------------------------
// Kernel 1: dtype-detect position_ids, argmax row 0, cos/sin tables.
// ---------------------------------------------------------------------------
__global__ void rope_setup_kernel(const int* __restrict__ p32) {
    __shared__ int sv[256], si[256];
    __shared__ int s_is64, s_idx;
    int t = threadIdx.x;

    if (t == 0) {
        int is64 = 1;
        for (int i = 1; i < 64; i += 2)
            if (p32[i] != 0) { is64 = 0; break; }
        s_is64 = is64;
    }
    __syncthreads();
    const int is64 = s_is64;
    const int stride = is64 ? 2 : 1;

    int bv = -2147483647, bi = 0;
    for (int i = t; i < LKV; i += 256) {
        int v = p32[i * stride];
        if (v > bv) { bv = v; bi = i; }
    }
    sv[t] = bv; si[t] = bi;
    __syncthreads();
    for (int off = 128; off > 0; off >>= 1) {
        if (t < off) {
            if (sv[t + off] > sv[t] || (sv[t + off] == sv[t] && si[t + off] < si[t])) {
                sv[t] = sv[t + off]; si[t] = si[t + off];
            }
        }
        __syncthreads();
    }
    if (t == 0) s_idx = si[0];
    __syncthreads();
    const int idx = s_idx;

    for (int i = t; i < NB * 64; i += 256) {
        int b = i >> 6, j = i & 63;
        long long pv;
        if (is64) pv = ((const long long*)p32)[b * LKV + idx];
        else      pv = (long long)p32[b * LKV + idx];
        double ang = (double)pv * pow(10000.0, -(double)j / 64.0);
        g_cos[i] = (float)cos(ang);
        g_sin[i] = (float)sin(ang);
    }
}

// ---------------------------------------------------------------------------
// GEMM1 (q_w): bf16 3-pass, double-buffered smem, 3-deep register pipeline.
// ---------------------------------------------------------------------------
#define GSTR 20
__global__ __launch_bounds__(256) void gemm_mma_kernel(
    const float* __restrict__ A, const float* __restrict__ W)
{
    __shared__ uint32_t Ah[2][64 * GSTR], Al[2][64 * GSTR];
    __shared__ uint32_t Wh[2][64 * GSTR], Wl[2][64 * GSTR];

    int t = threadIdx.x;
    int nb = blockIdx.x * 64;
    int ks = blockIdx.y;
    int k_begin = ks * KSLICE;
    int w = t >> 5, lane = t & 31;
    int g = lane >> 2, tig = lane & 3;
    int wm = (w & 3) * 16;
    int wn = (w >> 2) * 32;

    int row0 = t >> 3, kq0 = t & 7;
    int row1 = (t + 256) >> 3, kq1 = t & 7;

    float c[4][4] = {};
    float4 vaR[2][2], vwR[2][2];

    {
        float4 va0 = *(const float4*)(A + (size_t)row0 * HID + k_begin + kq0 * 4);
        float4 va1 = *(const float4*)(A + (size_t)row1 * HID + k_begin + kq1 * 4);
        float4 vw0 = *(const float4*)(W + (size_t)(nb + row0) * HID + k_begin + kq0 * 4);
        float4 vw1 = *(const float4*)(W + (size_t)(nb + row1) * HID + k_begin + kq1 * 4);
        uint32_t h0, l0, h1, l1;
        split2(va0.x, va0.y, h0, l0); split2(va0.z, va0.w, h1, l1);
        *(uint2*)&Ah[0][row0 * GSTR + kq0 * 2] = make_uint2(h0, h1);
        *(uint2*)&Al[0][row0 * GSTR + kq0 * 2] = make_uint2(l0, l1);
        split2(va1.x, va1.y, h0, l0); split2(va1.z, va1.w, h1, l1);
        *(uint2*)&Ah[0][row1 * GSTR + kq1 * 2] = make_uint2(h0, h1);
        *(uint2*)&Al[0][row1 * GSTR + kq1 * 2] = make_uint2(l0, l1);
        split2(vw0.x, vw0.y, h0, l0); split2(vw0.z, vw0.w, h1, l1);
        *(uint2*)&Wh[0][row0 * GSTR + kq0 * 2] = make_uint2(h0, h1);
        *(uint2*)&Wl[0][row0 * GSTR + kq0 * 2] = make_uint2(l0, l1);
        split2(vw1.x, vw1.y, h0, l0); split2(vw1.z, vw1.w, h1, l1);
        *(uint2*)&Wh[0][row1 * GSTR + kq1 * 2] = make_uint2(h0, h1);
        *(uint2*)&Wl[0][row1 * GSTR + kq1 * 2] = make_uint2(l0, l1);

        int kc = k_begin + 32;
        vaR[1][0] = *(const float4*)(A + (size_t)row0 * HID + kc + kq0 * 4);
        vaR[1][1] = *(const float4*)(A + (size_t)row1 * HID + kc + kq1 * 4);
        vwR[1][0] = *(const float4*)(W + (size_t)(nb + row0) * HID + kc + kq0 * 4);
        vwR[1][1] = *(const float4*)(W + (size_t)(nb + row1) * HID + kc + kq1 * 4);
    }
    __syncthreads();

#pragma unroll 2
    for (int it = 0; it < NIT; it++) {
        int s = it & 1;
        int sn = s ^ 1;
        int pn = (it + 1) & 1;
        int pf = it & 1;

        if (it + 2 < NIT) {
            int kc = k_begin + (it + 2) * 32;
            vaR[pf][0] = *(const float4*)(A + (size_t)row0 * HID + kc + kq0 * 4);
            vaR[pf][1] = *(const float4*)(A + (size_t)row1 * HID + kc + kq1 * 4);
            vwR[pf][0] = *(const float4*)(W + (size_t)(nb + row0) * HID + kc + kq0 * 4);
            vwR[pf][1] = *(const float4*)(W + (size_t)(nb + row1) * HID + kc + kq1 * 4);
        }

#pragma unroll
        for (int kstep = 0; kstep < 2; kstep++) {
            int base = kstep * 8;
            uint32_t ah0 = Ah[s][(wm + g) * GSTR + base + tig];
            uint32_t ah1 = Ah[s][(wm + g + 8) * GSTR + base + tig];
            uint32_t ah2 = Ah[s][(wm + g) * GSTR + base + tig + 4];
            uint32_t ah3 = Ah[s][(wm + g + 8) * GSTR + base + tig + 4];
            uint32_t al0 = Al[s][(wm + g) * GSTR + base + tig];
            uint32_t al1 = Al[s][(wm + g + 8) * GSTR + base + tig];
            uint32_t al2 = Al[s][(wm + g) * GSTR + base + tig + 4];
            uint32_t al3 = Al[s][(wm + g + 8) * GSTR + base + tig + 4];
#pragma unroll
            for (int nt = 0; nt < 4; nt++) {
                int nrow = wn + nt * 8 + g;
                uint32_t bh0 = Wh[s][nrow * GSTR + base + tig];
                uint32_t bh1 = Wh[s][nrow * GSTR + base + tig + 4];
                uint32_t bl0 = Wl[s][nrow * GSTR + base + tig];
                uint32_t bl1 = Wl[s][nrow * GSTR + base + tig + 4];
                mma_bf16(c[nt], ah0, ah1, ah2, ah3, bh0, bh1);
                mma_bf16(c[nt], ah0, ah1, ah2, ah3, bl0, bl1);
                mma_bf16(c[nt], al0, al1, al2, al3, bh0, bh1);
            }
        }

        if (it + 1 < NIT) {
            uint32_t h0, l0, h1, l1;
            split2(vaR[pn][0].x, vaR[pn][0].y, h0, l0);
            split2(vaR[pn][0].z, vaR[pn][0].w, h1, l1);
            *(uint2*)&Ah[sn][row0 * GSTR + kq0 * 2] = make_uint2(h0, h1);
            *(uint2*)&Al[sn][row0 * GSTR + kq0 * 2] = make_uint2(l0, l1);
            split2(vaR[pn][1].x, vaR[pn][1].y, h0, l0);
            split2(vaR[pn][1].z, vaR[pn][1].w, h1, l1);
            *(uint2*)&Ah[sn][row1 * GSTR + kq1 * 2] = make_uint2(h0, h1);
            *(uint2*)&Al[sn][row1 * GSTR + kq1 * 2] = make_uint2(l0, l1);
            split2(vwR[pn][0].x, vwR[pn][0].y, h0, l0);
            split2(vwR[pn][0].z, vwR[pn][0].w, h1, l1);
            *(uint2*)&Wh[sn][row0 * GSTR + kq0 * 2] = make_uint2(h0, h1);
            *(uint2*)&Wl[sn][row0 * GSTR + kq0 * 2] = make_uint2(l0, l1);
            split2(vwR[pn][1].x, vwR[pn][1].y, h0, l0);
            split2(vwR[pn][1].z, vwR[pn][1].w, h1, l1);
            *(uint2*)&Wh[sn][row1 * GSTR + kq1 * 2] = make_uint2(h0, h1);
            *(uint2*)&Wl[sn][row1 * GSTR + kq1 * 2] = make_uint2(l0, l1);
        }
        __syncthreads();
    }

    float* P = g_part + (size_t)ks * MR * HID;
#pragma unroll
    for (int nt = 0; nt < 4; nt++) {
        int col = nb + wn + nt * 8 + tig * 2;
        int r0 = wm + g, r1 = wm + g + 8;
        P[r0 * HID + col] = c[nt][0]; P[r0 * HID + col + 1] = c[nt][1];
        P[r1 * HID + col] = c[nt][2]; P[r1 * HID + col + 1] = c[nt][3];
    }
}

// ---------------------------------------------------------------------------
// GEMM2 (o_w): fp16 single-pass, same 3-deep pipeline.
// ---------------------------------------------------------------------------
__global__ __launch_bounds__(256) void gemm_f16_kernel(const float* __restrict__ W)
{
    const float* A = g_attn;

    __shared__ uint32_t Ahf[2][64 * GSTR], Whf[2][64 * GSTR];

    int t = threadIdx.x;
    int nb = blockIdx.x * 64;
    int ks = blockIdx.y;
    int k_begin = ks * KSLICE;
    int w = t >> 5, lane = t & 31;
    int g = lane >> 2, tig = lane & 3;
    int wm = (w & 3) * 16;
    int wn = (w >> 2) * 32;

    int row0 = t >> 3, kq0 = t & 7;
    int row1 = (t + 256) >> 3, kq1 = t & 7;

    float c[4][4] = {};
    float4 vaR[2][2], vwR[2][2];

    {
        float4 va0 = *(const float4*)(A + (size_t)row0 * HID + k_begin + kq0 * 4);
        float4 va1 = *(const float4*)(A + (size_t)row1 * HID + k_begin + kq1 * 4);
        float4 vw0 = *(const float4*)(W + (size_t)(nb + row0) * HID + k_begin + kq0 * 4);
        float4 vw1 = *(const float4*)(W + (size_t)(nb + row1) * HID + k_begin + kq1 * 4);
        *(uint2*)&Ahf[0][row0 * GSTR + kq0 * 2] =
            make_uint2(cvt_f16x2(va0.x, va0.y), cvt_f16x2(va0.z, va0.w));
        *(uint2*)&Ahf[0][row1 * GSTR + kq1 * 2] =
            make_uint2(cvt_f16x2(va1.x, va1.y), cvt_f16x2(va1.z, va1.w));
        *(uint2*)&Whf[0][row0 * GSTR + kq0 * 2] =
            make_uint2(cvt_f16x2(vw0.x, vw0.y), cvt_f16x2(vw0.z, vw0.w));
        *(uint2*)&Whf[0][row1 * GSTR + kq1 * 2] =
            make_uint2(cvt_f16x2(vw1.x, vw1.y), cvt_f16x2(vw1.z, vw1.w));

        int kc = k_begin + 32;
        vaR[1][0] = *(const float4*)(A + (size_t)row0 * HID + kc + kq0 * 4);
        vaR[1][1] = *(const float4*)(A + (size_t)row1 * HID + kc + kq1 * 4);
        vwR[1][0] = *(const float4*)(W + (size_t)(nb + row0) * HID + kc + kq0 * 4);
        vwR[1][1] = *(const float4*)(W + (size_t)(nb + row1) * HID + kc + kq1 * 4);
    }
    __syncthreads();

#pragma unroll 2
    for (int it = 0; it < NIT; it++) {
        int s = it & 1;
        int sn = s ^ 1;
        int pn = (it + 1) & 1;
        int pf = it & 1;

        if (it + 2 < NIT) {
            int kc = k_begin + (it + 2) * 32;
            vaR[pf][0] = *(const float4*)(A + (size_t)row0 * HID + kc + kq0 * 4);
            vaR[pf][1] = *(const float4*)(A + (size_t)row1 * HID + kc + kq1 * 4);
            vwR[pf][0] = *(const float4*)(W + (size_t)(nb + row0) * HID + kc + kq0 * 4);
            vwR[pf][1] = *(const float4*)(W + (size_t)(nb + row1) * HID + kc + kq1 * 4);
        }

#pragma unroll
        for (int kstep = 0; kstep < 2; kstep++) {
            int base = kstep * 8;
            uint32_t a0 = Ahf[s][(wm + g) * GSTR + base + tig];
            uint32_t a1 = Ahf[s][(wm + g + 8) * GSTR + base + tig];
            uint32_t a2 = Ahf[s][(wm + g) * GSTR + base + tig + 4];
            uint32_t a3 = Ahf[s][(wm + g + 8) * GSTR + base + tig + 4];
#pragma unroll
            for (int nt = 0; nt < 4; nt++) {
                int nrow = wn + nt * 8 + g;
                uint32_t b0 = Whf[s][nrow * GSTR + base + tig];
                uint32_t b1 = Whf[s][nrow * GSTR + base + tig + 4];
                mma_f16(c[nt], a0, a1, a2, a3, b0, b1);
            }
        }

        if (it + 1 < NIT) {
            *(uint2*)&Ahf[sn][row0 * GSTR + kq0 * 2] =
                make_uint2(cvt_f16x2(vaR[pn][0].x, vaR[pn][0].y),
                           cvt_f16x2(vaR[pn][0].z, vaR[pn][0].w));
            *(uint2*)&Ahf[sn][row1 * GSTR + kq1 * 2] =
                make_uint2(cvt_f16x2(vaR[pn][1].x, vaR[pn][1].y),
                           cvt_f16x2(vaR[pn][1].z, vaR[pn][1].w));
            *(uint2*)&Whf[sn][row0 * GSTR + kq0 * 2] =
                make_uint2(cvt_f16x2(vwR[pn][0].x, vwR[pn][0].y),
                           cvt_f16x2(vwR[pn][0].z, vwR[pn][0].w));
            *(uint2*)&Whf[sn][row1 * GSTR + kq1 * 2] =
                make_uint2(cvt_f16x2(vwR[pn][1].x, vwR[pn][1].y),
                           cvt_f16x2(vwR[pn][1].z, vwR[pn][1].w));
        }
        __syncthreads();
    }

    float* P = g_part + (size_t)ks * MR * HID;
#pragma unroll
    for (int nt = 0; nt < 4; nt++) {
        int col = nb + wn + nt * 8 + tig * 2;
        int r0 = wm + g, r1 = wm + g + 8;
        P[r0 * HID + col] = c[nt][0]; P[r0 * HID + col + 1] = c[nt][1];
        P[r1 * HID + col] = c[nt][2]; P[r1 * HID + col + 1] = c[nt][3];
    }
}

// ---------------------------------------------------------------------------
// Reduce GEMM1 partials + RoPE + scale by 1/sqrt(D) + relayout into g_q.
// ---------------------------------------------------------------------------
__global__ void rope_reduce_kernel() {
    const float scl = 0.08838834764831845f;  // 1/sqrt(128)
    int i = blockIdx.x * 256 + threadIdx.x;
    int dj = i & 63;
    int h = (i >> 6) & 31;
    int m = i >> 11;
    int c1 = h * DH + dj, c2 = c1 + 64;
    float x = 0.f, o = 0.f;
#pragma unroll
    for (int ks = 0; ks < KSPLIT; ks++) {
        x += g_part[ks * MR * HID + m * HID + c1];
        o += g_part[ks * MR * HID + m * HID + c2];
    }
    int b = m >> 3, qq = m & 7;
    float cc = g_cos[b * 64 + dj], ss = g_sin[b * 64 + dj];
    float v1 = (x * cc - o * ss) * scl;
    float v2 = (o * cc + x * ss) * scl;
    int kvh = h >> 2, gg = h & 3;
    int r = gg * NQ + qq;
    int bk = b * NKVH + kvh;
    g_q[(bk * 32 + r) * DH + dj] = v1;
    g_q[(bk * 32 + r) * DH + dj + 64] = v2;
}

// ---------------------------------------------------------------------------
// Reduce GEMM2 partials into d_out.
// ---------------------------------------------------------------------------
__global__ void reduce_out_kernel(float* __restrict__ out) {
    int i = blockIdx.x * 256 + threadIdx.x;
    float s = 0.f;
#pragma unroll
    for (int ks = 0; ks < KSPLIT; ks++)
        s += g_part[ks * MR * HID + i];
    out[i] = s;
}

// ---------------------------------------------------------------------------
// Split-KV flash attention: QK bf16 3-pass, PV fp16 single-pass,
// DOUBLE-BUFFERED K/V stages -> only 2 barriers per chunk:
//   [LDG ch+1] -> QK(stage s)+scores -> SYNC -> STS(ch+1 -> stage s^1)
//   -> softmax -> SYNC -> PV(stage s)
// Hazards: scores(sync1), stage s^1 WAR vs PV(ch-1) (program order + sync1),
// P/rs + stage s^1 publish (sync2).
// ---------------------------------------------------------------------------
#define QSTR 68    // Q/K row stride (64 words + 4 pad)
#define VSTR 17    // Vt row stride (16 spairs + 1)
#define SSTR 33    // score row stride
#define PSTR 17    // P row stride
#define KSTG 2176  // one K stage (32 rows x QSTR)
#define VSTG 2176  // one V stage (128 rows x VSTR)

#define OFF_QH 0
#define OFF_QL (OFF_QH + 32 * QSTR)          // 2176
#define OFF_KH (OFF_QL + 32 * QSTR)          // 4352  (2 stages)
#define OFF_KL (OFF_KH + 2 * KSTG)           // 8704  (2 stages)
#define OFF_VF (OFF_KL + 2 * KSTG)           // 13056 (2 stages)
#define OFF_SC (OFF_VF + 2 * VSTG)           // 17408
#define OFF_PF (OFF_SC + 32 * SSTR)          // 18464
#define OFF_AUX (OFF_PF + 32 * PSTR)         // 19008
#define SMEM_WORDS (OFF_AUX + 96)            // 19104 words = 76416 B

__global__ __launch_bounds__(256, 2) void attn_mma_kernel(
    const float* __restrict__ Kc, const float* __restrict__ Vc)
{
    extern __shared__ uint32_t sw[];
    uint32_t* Qh = sw + OFF_QH;
    uint32_t* Ql = sw + OFF_QL;
    float*    Sc = (float*)(sw + OFF_SC);
    uint32_t* Pf = sw + OFF_PF;
    float*    rm = (float*)(sw + OFF_AUX);
    float*    rl = rm + 32;
    float*    rs = rl + 32;

    int t = threadIdx.x;
    int w = t >> 5, lane = t & 31;
    int g = lane >> 2, tig = lane & 3;
    int sp = blockIdx.x & (NSPLIT - 1), bk = blockIdx.x >> 4;
    const float* Kb = Kc + (size_t)bk * LKV * DH;
    const float* Vb = Vc + (size_t)bk * LKV * DH;

    int qm = (w & 1) * 16;      // m-half
    int kn = (w >> 1) * 8;      // QK col base (8 cols per warp)
    int dB = (w >> 1) * 32;     // PV d base

    // per-thread K/V load coords
    int krow = t >> 3, kq4 = t & 7;            // K: row 0..31, quad 0..7

    float o[4][4] = {};
    float4 kreg[4];
    float  vreg[16];

    int s_base = sp * SPLIT_LEN;

    // ---- prologue: stage Q, load+STS chunk 0 into stage 0 ----
#pragma unroll
    for (int i = 0; i < 4; i++) {
        int f4 = t + i * 256;
        int row = f4 >> 5, q4 = f4 & 31;
        float4 v = *(const float4*)(g_q + (size_t)(bk * 32 + row) * DH + q4 * 4);
        uint32_t h0, l0, h1, l1;
        split2(v.x, v.y, h0, l0);
        split2(v.z, v.w, h1, l1);
        *(uint2*)&Qh[row * QSTR + q4 * 2] = make_uint2(h0, h1);
        *(uint2*)&Ql[row * QSTR + q4 * 2] = make_uint2(l0, l1);
    }
    if (t < 32) { rm[t] = -INFINITY; rl[t] = 0.f; }
    {
#pragma unroll
        for (int i = 0; i < 4; i++) {
            int f4 = t + i * 256;
            int row = f4 >> 5, q4 = f4 & 31;
            kreg[i] = *(const float4*)(Kb + (size_t)(s_base + row) * DH + q4 * 4);
        }
#pragma unroll
        for (int i = 0; i < 2; i++) {
            int spair = w + 8 * i;
#pragma unroll
            for (int j = 0; j < 4; j++) {
                int d = lane + 32 * j;
                vreg[i * 8 + j * 2]     = Vb[(size_t)(s_base + 2 * spair) * DH + d];
                vreg[i * 8 + j * 2 + 1] = Vb[(size_t)(s_base + 2 * spair + 1) * DH + d];
            }
        }
        // STS chunk 0 -> stage 0
        uint32_t* KhS = sw + OFF_KH;
        uint32_t* KlS = sw + OFF_KL;
        uint32_t* VfS = sw + OFF_VF;
#pragma unroll
        for (int i = 0; i < 4; i++) {
            int f4 = t + i * 256;
            int row = f4 >> 5, q4 = f4 & 31;
            uint32_t h0, l0, h1, l1;
            split2(kreg[i].x, kreg[i].y, h0, l0);
            split2(kreg[i].z, kreg[i].w, h1, l1);
            *(uint2*)&KhS[row * QSTR + q4 * 2] = make_uint2(h0, h1);
            *(uint2*)&KlS[row * QSTR + q4 * 2] = make_uint2(l0, l1);
        }
#pragma unroll
        for (int i = 0; i < 2; i++) {
            int spair = w + 8 * i;
#pragma unroll
            for (int j = 0; j < 4; j++) {
                int d = lane + 32 * j;
                VfS[d * VSTR + spair] = cvt_f16x2(vreg[i * 8 + j * 2], vreg[i * 8 + j * 2 + 1]);
            }
        }
    }
    __syncthreads();

    for (int ch = 0; ch < NCH; ch++) {
        int stg = ch & 1;
        int sc0 = s_base + ch * CS;
        uint32_t* KhS = sw + OFF_KH + stg * KSTG;
        uint32_t* KlS = sw + OFF_KL + stg * KSTG;
        uint32_t* VfS = sw + OFF_VF + stg * VSTG;
        uint32_t* KhN = sw + OFF_KH + (stg ^ 1) * KSTG;
        uint32_t* KlN = sw + OFF_KL + (stg ^ 1) * KSTG;
        uint32_t* VfN = sw + OFF_VF + (stg ^ 1) * VSTG;

        // 1. prefetch chunk ch+1 (LDG -> regs; covered by QK below)
        bool have_next = (ch + 1 < NCH);
        if (have_next) {
            int sn = sc0 + CS;
#pragma unroll
            for (int i = 0; i < 4; i++) {
                int f4 = t + i * 256;
                int row = f4 >> 5, q4 = f4 & 31;
                kreg[i] = *(const float4*)(Kb + (size_t)(sn + row) * DH + q4 * 4);
            }
#pragma unroll
            for (int i = 0; i < 2; i++) {
                int spair = w + 8 * i;
#pragma unroll
                for (int j = 0; j < 4; j++) {
                    int d = lane + 32 * j;
                    vreg[i * 8 + j * 2]     = Vb[(size_t)(sn + 2 * spair) * DH + d];
                    vreg[i * 8 + j * 2 + 1] = Vb[(size_t)(sn + 2 * spair + 1) * DH + d];
                }
            }
        }

        // 2. QK^T: 16 q-rows x 8 s-cols per warp (bf16 3-pass), from stage stg
        float s4[4] = {0.f, 0.f, 0.f, 0.f};
#pragma unroll
        for (int ksd = 0; ksd < 8; ksd++) {
            int base = ksd * 8;
            int srow = kn + g;
            uint32_t ah0 = Qh[(qm + g) * QSTR + base + tig];
            uint32_t ah1 = Qh[(qm + g + 8) * QSTR + base + tig];
            uint32_t ah2 = Qh[(qm + g) * QSTR + base + tig + 4];
            uint32_t ah3 = Qh[(qm + g + 8) * QSTR + base + tig + 4];
            uint32_t al0 = Ql[(qm + g) * QSTR + base + tig];
            uint32_t al1 = Ql[(qm + g + 8) * QSTR + base + tig];
            uint32_t al2 = Ql[(qm + g) * QSTR + base + tig + 4];
            uint32_t al3 = Ql[(qm + g + 8) * QSTR + base + tig + 4];
            uint32_t bh0 = KhS[srow * QSTR + base + tig];
            uint32_t bh1 = KhS[srow * QSTR + base + tig + 4];
            uint32_t bl0 = KlS[srow * QSTR + base + tig];
            uint32_t bl1 = KlS[srow * QSTR + base + tig + 4];
            mma_bf16(s4, ah0, ah1, ah2, ah3, bh0, bh1);
            mma_bf16(s4, ah0, ah1, ah2, ah3, bl0, bl1);
            mma_bf16(s4, al0, al1, al2, al3, bh0, bh1);
        }
        {
            int col = kn + tig * 2;
            int r0 = qm + g, r1 = qm + g + 8;
            int sg0 = sc0 + col, sg1 = sg0 + 1;
            float v00 = s4[0], v01 = s4[1], v10 = s4[2], v11 = s4[3];
            if (sg0 > 4088 + (r0 & 7)) v00 = -10000.f;
            if (sg1 > 4088 + (r0 & 7)) v01 = -10000.f;
            if (sg0 > 4088 + (r1 & 7)) v10 = -10000.f;
            if (sg1 > 4088 + (r1 & 7)) v11 = -10000.f;
            Sc[r0 * SSTR + col] = v00; Sc[r0 * SSTR + col + 1] = v01;
            Sc[r1 * SSTR + col] = v10; Sc[r1 * SSTR + col + 1] = v11;
        }
        __syncthreads();   // sync 1: scores visible; all PV(ch-1) done (program order)

        // 4. convert + STS chunk ch+1 into the OTHER stage
        if (have_next) {
#pragma unroll
            for (int i = 0; i < 4; i++) {
                int f4 = t + i * 256;
                int row = f4 >> 5, q4 = f4 & 31;
                uint32_t h0, l0, h1, l1;
                split2(kreg[i].x, kreg[i].y, h0, l0);
                split2(kreg[i].z, kreg[i].w, h1, l1);
                *(uint2*)&KhN[row * QSTR + q4 * 2] = make_uint2(h0, h1);
                *(uint2*)&KlN[row * QSTR + q4 * 2] = make_uint2(l0, l1);
            }
#pragma unroll
            for (int i = 0; i < 2; i++) {
                int spair = w + 8 * i;
#pragma unroll
                for (int j = 0; j < 4; j++) {
                    int d = lane + 32 * j;
                    VfN[d * VSTR + spair] = cvt_f16x2(vreg[i * 8 + j * 2], vreg[i * 8 + j * 2 + 1]);
                }
            }
        }

        // 5. online softmax: warp w owns rows w*4 .. w*4+3 (32 cols each)
#pragma unroll
        for (int k2 = 0; k2 < 4; k2++) {
            int rr = w * 4 + k2;
            float v = Sc[rr * SSTR + lane];
            float mx = v;
#pragma unroll
            for (int off = 16; off > 0; off >>= 1)
                mx = fmaxf(mx, __shfl_xor_sync(0xffffffffu, mx, off));
            float mprev = rm[rr];
            float mnew = fmaxf(mprev, mx);
            float p = __expf(v - mnew);
            float ls = p;
#pragma unroll
            for (int off = 16; off > 0; off >>= 1)
                ls += __shfl_xor_sync(0xffffffffu, ls, off);
            float pe = __shfl_sync(0xffffffffu, p, (lane & 15) * 2);
            float po = __shfl_sync(0xffffffffu, p, (lane & 15) * 2 + 1);
            if (lane < 16) {
                Pf[rr * PSTR + lane] = cvt_f16x2(pe, po);
            }
            if (lane == 0) {
                float f = __expf(mprev - mnew);
                rl[rr] = rl[rr] * f + ls;
                rm[rr] = mnew;
                rs[rr] = f;
            }
        }
        __syncthreads();   // sync 2: P/rs visible; stage s^1 published for next QK

        // 7. rescale + PV (fp16) from stage stg
        float f0 = rs[qm + g], f1 = rs[qm + g + 8];
#pragma unroll
        for (int nt = 0; nt < 4; nt++) {
            o[nt][0] *= f0; o[nt][1] *= f0;
            o[nt][2] *= f1; o[nt][3] *= f1;
        }
#pragma unroll
        for (int kstep = 0; kstep < 2; kstep++) {
            int base = kstep * 8;
            uint32_t p0 = Pf[(qm + g) * PSTR + base + tig];
            uint32_t p1 = Pf[(qm + g + 8) * PSTR + base + tig];
            uint32_t p2 = Pf[(qm + g) * PSTR + base + tig + 4];
            uint32_t p3 = Pf[(qm + g + 8) * PSTR + base + tig + 4];
#pragma unroll
            for (int nt = 0; nt < 4; nt++) {
                int drow = dB + nt * 8 + g;
                uint32_t b0 = VfS[drow * VSTR + base + tig];
                uint32_t b1 = VfS[drow * VSTR + base + tig + 4];
                mma_f16(o[nt], p0, p1, p2, p3, b0, b1);
            }
        }
    }

    int pbase = (bk * NSPLIT + sp) * 32;
    if (t < 32) { g_pm[pbase + t] = rm[t]; g_pl[pbase + t] = rl[t]; }
#pragma unroll
    for (int nt = 0; nt < 4; nt++) {
        int col = dB + nt * 8 + tig * 2;
        int r0 = qm + g, r1 = qm + g + 8;
        g_po[(size_t)(pbase + r0) * DH + col]     = o[nt][0];
        g_po[(size_t)(pbase + r0) * DH + col + 1] = o[nt][1];
        g_po[(size_t)(pbase + r1) * DH + col]     = o[nt][2];
        g_po[(size_t)(pbase + r1) * DH + col + 1] = o[nt][3];
    }
}

// ---------------------------------------------------------------------------
// Merge split partials (log-sum-exp) + relayout to [(b,qq)][h*128+d]
// ---------------------------------------------------------------------------
__global__ void merge_kernel() {
    int i = blockIdx.x * 256 + threadIdx.x;   // 0 .. 262143
    int d = i & 127;
    int rg = i >> 7;
    int bk = rg >> 5, r = rg & 31;
    float mv[NSPLIT];
    float mmax = -INFINITY;
#pragma unroll
    for (int sp = 0; sp < NSPLIT; sp++) {
        mv[sp] = g_pm[(bk * NSPLIT + sp) * 32 + r];
        mmax = fmaxf(mmax, mv[sp]);
    }
    float num = 0.f, den = 0.f;
#pragma unroll
    for (int sp = 0; sp < NSPLIT; sp++) {
        float wgt = __expf(mv[sp] - mmax);
        num += wgt * g_po[(size_t)((bk * NSPLIT + sp) * 32 + r) * DH + d];
        den += wgt * g_pl[(bk * NSPLIT + sp) * 32 + r];
    }
    float val = num / den;
    int b = bk >> 3, kvh = bk & 7, gg = r >> 3, qq = r & 7;
    int h = kvh * NG + gg;
    g_attn[(b * NQ + qq) * HID + h * DH + d] = val;
}

// ---------------------------------------------------------------------------
// kernel_launch
// ---------------------------------------------------------------------------
extern "C" void kernel_launch(void* const* d_in, const int* in_sizes, int n_in,
                              void* d_out, int out_size) {
    (void)in_sizes; (void)n_in; (void)out_size;
    const float* hidden = (const float*)d_in[0];
    const int* pos = (const int*)d_in[1];
    const float* kc = (const float*)d_in[2];
    const float* vc = (const float*)d_in[3];
    const float* qw = (const float*)d_in[5];
    const float* ow = (const float*)d_in[6];
    float* out = (float*)d_out;

    static int attr_done = 0;
    if (!attr_done) {
        cudaFuncSetAttribute(attn_mma_kernel,
                             cudaFuncAttributeMaxDynamicSharedMemorySize,
                             SMEM_WORDS * 4);
        attr_done = 1;
    }

    rope_setup_kernel<<<1, 256>>>(pos);
    gemm_mma_kernel<<<dim3(HID / 64, KSPLIT), 256>>>(hidden, qw);
    rope_reduce_kernel<<<512, 256>>>();
    attn_mma_kernel<<<64 * NSPLIT, 256, SMEM_WORDS * 4>>>(kc, vc);
    merge_kernel<<<1024, 256>>>();
    gemm_f16_kernel<<<dim3(HID / 64, KSPLIT), 256>>>(ow);
    reduce_out_kernel<<<1024, 256>>>(out);
}

// round 15
// speedup vs baseline: 1.0665x; 1.0665x over previous
#include <cuda_runtime.h>
#include <cuda_bf16.h>
#include <math.h>
#include <stdint.h>

// Problem constants
#define NB 8
#define NQ 8
#define HID 4096
#define NH 32
#define NKVH 8
#define NG 4
#define DH 128
#define LKV 4096
#define NSPLIT 16
#define MR 64                    // B*Q rows
#define SPLIT_LEN (LKV / NSPLIT) // 256
#define CS 64                    // keys per chunk
#define NCH (SPLIT_LEN / CS)     // 4
#define KSPLIT 4                 // GEMM k-split (256 blocks -> single wave)
#define KSLICE (HID / KSPLIT)    // 1024
#define NIT (KSLICE / 32)        // 32 k-iterations per block

// Scratch (device globals — no allocation allowed)
__device__ float g_part[KSPLIT * MR * HID];             // GEMM split-K partials (4MB)
__device__ float g_q[MR * HID];                         // roped+scaled Q, [bk][r][d]
__device__ float g_attn[MR * HID];                      // merged attn out [(b,qq)][h*128+d]
__device__ float g_po[NB * NKVH * NSPLIT * 32 * DH];    // partial O (unnormalized)
__device__ float g_pm[NB * NKVH * NSPLIT * 32];
__device__ float g_pl[NB * NKVH * NSPLIT * 32];
__device__ float g_cos[NB * 64];
__device__ float g_sin[NB * 64];

// ---------------------------------------------------------------------------
// FAST bf16 hi/lo split (packed cvt) + fp16 single cvt + mma helpers
// ---------------------------------------------------------------------------
__device__ __forceinline__ void split2(float x, float y, uint32_t& hi, uint32_t& lo) {
    asm("cvt.rn.bf16x2.f32 %0, %1, %2;" : "=r"(hi) : "f"(y), "f"(x));
    float hx = __uint_as_float(hi << 16);           // bf16(x) as float
    float hy = __uint_as_float(hi & 0xFFFF0000u);   // bf16(y) as float
    float lx = x - hx, ly = y - hy;
    asm("cvt.rn.bf16x2.f32 %0, %1, %2;" : "=r"(lo) : "f"(ly), "f"(lx));
}

__device__ __forceinline__ uint32_t cvt_f16x2(float x, float y) {
    uint32_t r;
    asm("cvt.rn.f16x2.f32 %0, %1, %2;" : "=r"(r) : "f"(y), "f"(x));  // x in low half
    return r;
}

__device__ __forceinline__ void mma_bf16(float c[4],
                                         uint32_t a0, uint32_t a1, uint32_t a2, uint32_t a3,
                                         uint32_t b0, uint32_t b1) {
    asm volatile(
        "mma.sync.aligned.m16n8k16.row.col.f32.bf16.bf16.f32 "
        "{%0,%1,%2,%3}, {%4,%5,%6,%7}, {%8,%9}, {%0,%1,%2,%3};\n"
        : "+f"(c[0]), "+f"(c[1]), "+f"(c[2]), "+f"(c[3])
        : "r"(a0), "r"(a1), "r"(a2), "r"(a3), "r"(b0), "r"(b1));
}

__device__ __forceinline__ void mma_f16(float c[4],
                                        uint32_t a0, uint32_t a1, uint32_t a2, uint32_t a3,
                                        uint32_t b0, uint32_t b1) {
    asm volatile(
        "mma.sync.aligned.m16n8k16.row.col.f32.f16.f16.f32 "
        "{%0,%1,%2,%3}, {%4,%5,%6,%7}, {%8,%9}, {%0,%1,%2,%3};\n"
        : "+f"(c[0]), "+f"(c[1]), "+f"(c[2]), "+f"(c[3])
        : "r"(a0), "r"(a1), "r"(a2), "r"(a3), "r"(b0), "r"(b1));
}

// ---------------------------------------------------------------------------
// Kernel 1: dtype-detect position_ids, argmax row 0, cos/sin tables.
// ---------------------------------------------------------------------------
__global__ void rope_setup_kernel(const int* __restrict__ p32) {
    __shared__ int sv[256], si[256];
    __shared__ int s_is64, s_idx;
    int t = threadIdx.x;

    if (t == 0) {
        int is64 = 1;
        for (int i = 1; i < 64; i += 2)
            if (p32[i] != 0) { is64 = 0; break; }
        s_is64 = is64;
    }
    __syncthreads();
    const int is64 = s_is64;
    const int stride = is64 ? 2 : 1;

    int bv = -2147483647, bi = 0;
    for (int i = t; i < LKV; i += 256) {
        int v = p32[i * stride];
        if (v > bv) { bv = v; bi = i; }
    }
    sv[t] = bv; si[t] = bi;
    __syncthreads();
    for (int off = 128; off > 0; off >>= 1) {
        if (t < off) {
            if (sv[t + off] > sv[t] || (sv[t + off] == sv[t] && si[t + off] < si[t])) {
                sv[t] = sv[t + off]; si[t] = si[t + off];
            }
        }
        __syncthreads();
    }
    if (t == 0) s_idx = si[0];
    __syncthreads();
    const int idx = s_idx;

    for (int i = t; i < NB * 64; i += 256) {
        int b = i >> 6, j = i & 63;
        long long pv;
        if (is64) pv = ((const long long*)p32)[b * LKV + idx];
        else      pv = (long long)p32[b * LKV + idx];
        double ang = (double)pv * pow(10000.0, -(double)j / 64.0);
        g_cos[i] = (float)cos(ang);
        g_sin[i] = (float)sin(ang);
    }
}

// ---------------------------------------------------------------------------
// GEMM1 (q_w): bf16 3-pass, double-buffered smem, 3-deep register pipeline.
// ---------------------------------------------------------------------------
#define GSTR 20
__global__ __launch_bounds__(256) void gemm_mma_kernel(
    const float* __restrict__ A, const float* __restrict__ W)
{
    __shared__ uint32_t Ah[2][64 * GSTR], Al[2][64 * GSTR];
    __shared__ uint32_t Wh[2][64 * GSTR], Wl[2][64 * GSTR];

    int t = threadIdx.x;
    int nb = blockIdx.x * 64;
    int ks = blockIdx.y;
    int k_begin = ks * KSLICE;
    int w = t >> 5, lane = t & 31;
    int g = lane >> 2, tig = lane & 3;
    int wm = (w & 3) * 16;
    int wn = (w >> 2) * 32;

    int row0 = t >> 3, kq0 = t & 7;
    int row1 = (t + 256) >> 3, kq1 = t & 7;

    float c[4][4] = {};
    float4 vaR[2][2], vwR[2][2];

    {
        float4 va0 = *(const float4*)(A + (size_t)row0 * HID + k_begin + kq0 * 4);
        float4 va1 = *(const float4*)(A + (size_t)row1 * HID + k_begin + kq1 * 4);
        float4 vw0 = *(const float4*)(W + (size_t)(nb + row0) * HID + k_begin + kq0 * 4);
        float4 vw1 = *(const float4*)(W + (size_t)(nb + row1) * HID + k_begin + kq1 * 4);
        uint32_t h0, l0, h1, l1;
        split2(va0.x, va0.y, h0, l0); split2(va0.z, va0.w, h1, l1);
        *(uint2*)&Ah[0][row0 * GSTR + kq0 * 2] = make_uint2(h0, h1);
        *(uint2*)&Al[0][row0 * GSTR + kq0 * 2] = make_uint2(l0, l1);
        split2(va1.x, va1.y, h0, l0); split2(va1.z, va1.w, h1, l1);
        *(uint2*)&Ah[0][row1 * GSTR + kq1 * 2] = make_uint2(h0, h1);
        *(uint2*)&Al[0][row1 * GSTR + kq1 * 2] = make_uint2(l0, l1);
        split2(vw0.x, vw0.y, h0, l0); split2(vw0.z, vw0.w, h1, l1);
        *(uint2*)&Wh[0][row0 * GSTR + kq0 * 2] = make_uint2(h0, h1);
        *(uint2*)&Wl[0][row0 * GSTR + kq0 * 2] = make_uint2(l0, l1);
        split2(vw1.x, vw1.y, h0, l0); split2(vw1.z, vw1.w, h1, l1);
        *(uint2*)&Wh[0][row1 * GSTR + kq1 * 2] = make_uint2(h0, h1);
        *(uint2*)&Wl[0][row1 * GSTR + kq1 * 2] = make_uint2(l0, l1);

        int kc = k_begin + 32;
        vaR[1][0] = *(const float4*)(A + (size_t)row0 * HID + kc + kq0 * 4);
        vaR[1][1] = *(const float4*)(A + (size_t)row1 * HID + kc + kq1 * 4);
        vwR[1][0] = *(const float4*)(W + (size_t)(nb + row0) * HID + kc + kq0 * 4);
        vwR[1][1] = *(const float4*)(W + (size_t)(nb + row1) * HID + kc + kq1 * 4);
    }
    __syncthreads();

#pragma unroll 2
    for (int it = 0; it < NIT; it++) {
        int s = it & 1;
        int sn = s ^ 1;
        int pn = (it + 1) & 1;
        int pf = it & 1;

        if (it + 2 < NIT) {
            int kc = k_begin + (it + 2) * 32;
            vaR[pf][0] = *(const float4*)(A + (size_t)row0 * HID + kc + kq0 * 4);
            vaR[pf][1] = *(const float4*)(A + (size_t)row1 * HID + kc + kq1 * 4);
            vwR[pf][0] = *(const float4*)(W + (size_t)(nb + row0) * HID + kc + kq0 * 4);
            vwR[pf][1] = *(const float4*)(W + (size_t)(nb + row1) * HID + kc + kq1 * 4);
        }

#pragma unroll
        for (int kstep = 0; kstep < 2; kstep++) {
            int base = kstep * 8;
            uint32_t ah0 = Ah[s][(wm + g) * GSTR + base + tig];
            uint32_t ah1 = Ah[s][(wm + g + 8) * GSTR + base + tig];
            uint32_t ah2 = Ah[s][(wm + g) * GSTR + base + tig + 4];
            uint32_t ah3 = Ah[s][(wm + g + 8) * GSTR + base + tig + 4];
            uint32_t al0 = Al[s][(wm + g) * GSTR + base + tig];
            uint32_t al1 = Al[s][(wm + g + 8) * GSTR + base + tig];
            uint32_t al2 = Al[s][(wm + g) * GSTR + base + tig + 4];
            uint32_t al3 = Al[s][(wm + g + 8) * GSTR + base + tig + 4];
#pragma unroll
            for (int nt = 0; nt < 4; nt++) {
                int nrow = wn + nt * 8 + g;
                uint32_t bh0 = Wh[s][nrow * GSTR + base + tig];
                uint32_t bh1 = Wh[s][nrow * GSTR + base + tig + 4];
                uint32_t bl0 = Wl[s][nrow * GSTR + base + tig];
                uint32_t bl1 = Wl[s][nrow * GSTR + base + tig + 4];
                mma_bf16(c[nt], ah0, ah1, ah2, ah3, bh0, bh1);
                mma_bf16(c[nt], ah0, ah1, ah2, ah3, bl0, bl1);
                mma_bf16(c[nt], al0, al1, al2, al3, bh0, bh1);
            }
        }

        if (it + 1 < NIT) {
            uint32_t h0, l0, h1, l1;
            split2(vaR[pn][0].x, vaR[pn][0].y, h0, l0);
            split2(vaR[pn][0].z, vaR[pn][0].w, h1, l1);
            *(uint2*)&Ah[sn][row0 * GSTR + kq0 * 2] = make_uint2(h0, h1);
            *(uint2*)&Al[sn][row0 * GSTR + kq0 * 2] = make_uint2(l0, l1);
            split2(vaR[pn][1].x, vaR[pn][1].y, h0, l0);
            split2(vaR[pn][1].z, vaR[pn][1].w, h1, l1);
            *(uint2*)&Ah[sn][row1 * GSTR + kq1 * 2] = make_uint2(h0, h1);
            *(uint2*)&Al[sn][row1 * GSTR + kq1 * 2] = make_uint2(l0, l1);
            split2(vwR[pn][0].x, vwR[pn][0].y, h0, l0);
            split2(vwR[pn][0].z, vwR[pn][0].w, h1, l1);
            *(uint2*)&Wh[sn][row0 * GSTR + kq0 * 2] = make_uint2(h0, h1);
            *(uint2*)&Wl[sn][row0 * GSTR + kq0 * 2] = make_uint2(l0, l1);
            split2(vwR[pn][1].x, vwR[pn][1].y, h0, l0);
            split2(vwR[pn][1].z, vwR[pn][1].w, h1, l1);
            *(uint2*)&Wh[sn][row1 * GSTR + kq1 * 2] = make_uint2(h0, h1);
            *(uint2*)&Wl[sn][row1 * GSTR + kq1 * 2] = make_uint2(l0, l1);
        }
        __syncthreads();
    }

    float* P = g_part + (size_t)ks * MR * HID;
#pragma unroll
    for (int nt = 0; nt < 4; nt++) {
        int col = nb + wn + nt * 8 + tig * 2;
        int r0 = wm + g, r1 = wm + g + 8;
        P[r0 * HID + col] = c[nt][0]; P[r0 * HID + col + 1] = c[nt][1];
        P[r1 * HID + col] = c[nt][2]; P[r1 * HID + col + 1] = c[nt][3];
    }
}

// ---------------------------------------------------------------------------
// GEMM2 (o_w): fp16 single-pass, same 3-deep pipeline.
// ---------------------------------------------------------------------------
__global__ __launch_bounds__(256) void gemm_f16_kernel(const float* __restrict__ W)
{
    const float* A = g_attn;

    __shared__ uint32_t Ahf[2][64 * GSTR], Whf[2][64 * GSTR];

    int t = threadIdx.x;
    int nb = blockIdx.x * 64;
    int ks = blockIdx.y;
    int k_begin = ks * KSLICE;
    int w = t >> 5, lane = t & 31;
    int g = lane >> 2, tig = lane & 3;
    int wm = (w & 3) * 16;
    int wn = (w >> 2) * 32;

    int row0 = t >> 3, kq0 = t & 7;
    int row1 = (t + 256) >> 3, kq1 = t & 7;

    float c[4][4] = {};
    float4 vaR[2][2], vwR[2][2];

    {
        float4 va0 = *(const float4*)(A + (size_t)row0 * HID + k_begin + kq0 * 4);
        float4 va1 = *(const float4*)(A + (size_t)row1 * HID + k_begin + kq1 * 4);
        float4 vw0 = *(const float4*)(W + (size_t)(nb + row0) * HID + k_begin + kq0 * 4);
        float4 vw1 = *(const float4*)(W + (size_t)(nb + row1) * HID + k_begin + kq1 * 4);
        *(uint2*)&Ahf[0][row0 * GSTR + kq0 * 2] =
            make_uint2(cvt_f16x2(va0.x, va0.y), cvt_f16x2(va0.z, va0.w));
        *(uint2*)&Ahf[0][row1 * GSTR + kq1 * 2] =
            make_uint2(cvt_f16x2(va1.x, va1.y), cvt_f16x2(va1.z, va1.w));
        *(uint2*)&Whf[0][row0 * GSTR + kq0 * 2] =
            make_uint2(cvt_f16x2(vw0.x, vw0.y), cvt_f16x2(vw0.z, vw0.w));
        *(uint2*)&Whf[0][row1 * GSTR + kq1 * 2] =
            make_uint2(cvt_f16x2(vw1.x, vw1.y), cvt_f16x2(vw1.z, vw1.w));

        int kc = k_begin + 32;
        vaR[1][0] = *(const float4*)(A + (size_t)row0 * HID + kc + kq0 * 4);
        vaR[1][1] = *(const float4*)(A + (size_t)row1 * HID + kc + kq1 * 4);
        vwR[1][0] = *(const float4*)(W + (size_t)(nb + row0) * HID + kc + kq0 * 4);
        vwR[1][1] = *(const float4*)(W + (size_t)(nb + row1) * HID + kc + kq1 * 4);
    }
    __syncthreads();

#pragma unroll 2
    for (int it = 0; it < NIT; it++) {
        int s = it & 1;
        int sn = s ^ 1;
        int pn = (it + 1) & 1;
        int pf = it & 1;

        if (it + 2 < NIT) {
            int kc = k_begin + (it + 2) * 32;
            vaR[pf][0] = *(const float4*)(A + (size_t)row0 * HID + kc + kq0 * 4);
            vaR[pf][1] = *(const float4*)(A + (size_t)row1 * HID + kc + kq1 * 4);
            vwR[pf][0] = *(const float4*)(W + (size_t)(nb + row0) * HID + kc + kq0 * 4);
            vwR[pf][1] = *(const float4*)(W + (size_t)(nb + row1) * HID + kc + kq1 * 4);
        }

#pragma unroll
        for (int kstep = 0; kstep < 2; kstep++) {
            int base = kstep * 8;
            uint32_t a0 = Ahf[s][(wm + g) * GSTR + base + tig];
            uint32_t a1 = Ahf[s][(wm + g + 8) * GSTR + base + tig];
            uint32_t a2 = Ahf[s][(wm + g) * GSTR + base + tig + 4];
            uint32_t a3 = Ahf[s][(wm + g + 8) * GSTR + base + tig + 4];
#pragma unroll
            for (int nt = 0; nt < 4; nt++) {
                int nrow = wn + nt * 8 + g;
                uint32_t b0 = Whf[s][nrow * GSTR + base + tig];
                uint32_t b1 = Whf[s][nrow * GSTR + base + tig + 4];
                mma_f16(c[nt], a0, a1, a2, a3, b0, b1);
            }
        }

        if (it + 1 < NIT) {
            *(uint2*)&Ahf[sn][row0 * GSTR + kq0 * 2] =
                make_uint2(cvt_f16x2(vaR[pn][0].x, vaR[pn][0].y),
                           cvt_f16x2(vaR[pn][0].z, vaR[pn][0].w));
            *(uint2*)&Ahf[sn][row1 * GSTR + kq1 * 2] =
                make_uint2(cvt_f16x2(vaR[pn][1].x, vaR[pn][1].y),
                           cvt_f16x2(vaR[pn][1].z, vaR[pn][1].w));
            *(uint2*)&Whf[sn][row0 * GSTR + kq0 * 2] =
                make_uint2(cvt_f16x2(vwR[pn][0].x, vwR[pn][0].y),
                           cvt_f16x2(vwR[pn][0].z, vwR[pn][0].w));
            *(uint2*)&Whf[sn][row1 * GSTR + kq1 * 2] =
                make_uint2(cvt_f16x2(vwR[pn][1].x, vwR[pn][1].y),
                           cvt_f16x2(vwR[pn][1].z, vwR[pn][1].w));
        }
        __syncthreads();
    }

    float* P = g_part + (size_t)ks * MR * HID;
#pragma unroll
    for (int nt = 0; nt < 4; nt++) {
        int col = nb + wn + nt * 8 + tig * 2;
        int r0 = wm + g, r1 = wm + g + 8;
        P[r0 * HID + col] = c[nt][0]; P[r0 * HID + col + 1] = c[nt][1];
        P[r1 * HID + col] = c[nt][2]; P[r1 * HID + col + 1] = c[nt][3];
    }
}

// ---------------------------------------------------------------------------
// Reduce GEMM1 partials + RoPE + scale by 1/sqrt(D) + relayout into g_q.
// ---------------------------------------------------------------------------
__global__ void rope_reduce_kernel() {
    const float scl = 0.08838834764831845f;  // 1/sqrt(128)
    int i = blockIdx.x * 256 + threadIdx.x;
    int dj = i & 63;
    int h = (i >> 6) & 31;
    int m = i >> 11;
    int c1 = h * DH + dj, c2 = c1 + 64;
    float x = 0.f, o = 0.f;
#pragma unroll
    for (int ks = 0; ks < KSPLIT; ks++) {
        x += g_part[ks * MR * HID + m * HID + c1];
        o += g_part[ks * MR * HID + m * HID + c2];
    }
    int b = m >> 3, qq = m & 7;
    float cc = g_cos[b * 64 + dj], ss = g_sin[b * 64 + dj];
    float v1 = (x * cc - o * ss) * scl;
    float v2 = (o * cc + x * ss) * scl;
    int kvh = h >> 2, gg = h & 3;
    int r = gg * NQ + qq;
    int bk = b * NKVH + kvh;
    g_q[(bk * 32 + r) * DH + dj] = v1;
    g_q[(bk * 32 + r) * DH + dj + 64] = v2;
}

// ---------------------------------------------------------------------------
// Reduce GEMM2 partials into d_out.
// ---------------------------------------------------------------------------
__global__ void reduce_out_kernel(float* __restrict__ out) {
    int i = blockIdx.x * 256 + threadIdx.x;
    float s = 0.f;
#pragma unroll
    for (int ks = 0; ks < KSPLIT; ks++)
        s += g_part[ks * MR * HID + i];
    out[i] = s;
}

// ---------------------------------------------------------------------------
// Split-KV flash attention: QK bf16 3-pass, PV fp16 single-pass, CS=64:
// each warp owns 16 q-rows x 16 s-cols -> one Q fragment feeds 2 K col-groups
// (Q LDS per key halves); softmax/barriers per key halve. V prefetch is
// converted to fp16 at load time (vreg: 16 u32).
// 1024 blocks (64 bk x 16 splits), 256 thr (8 warps), 2 CTAs/SM.
// ---------------------------------------------------------------------------
#define QSTR 68    // Q/K row stride (64 words + 4 pad) -> frag banks 4g+t
#define VSTR 36    // Vt row stride (32 spairs + 4)     -> frag banks 4g+t
#define SSTR 66    // score row stride (64 + 2)
#define PSTR 36    // P row stride (32 + 4)

#define OFF_QH 0
#define OFF_QL (OFF_QH + 32 * QSTR)          // 2176
#define OFF_KH (OFF_QL + 32 * QSTR)          // 4352 (64 rows)
#define OFF_KL (OFF_KH + 64 * QSTR)          // 8704
#define OFF_VF (OFF_KL + 64 * QSTR)          // 13056 (fp16 V, 128 x 36)
#define OFF_SC (OFF_VF + 128 * VSTR)         // 17664
#define OFF_PF (OFF_SC + 32 * SSTR)          // 19776 (fp16 P, 32 x 36)
#define OFF_AUX (OFF_PF + 32 * PSTR)         // 20928
#define SMEM_WORDS (OFF_AUX + 96)            // 21024 words = 84096 B

__global__ __launch_bounds__(256, 2) void attn_mma_kernel(
    const float* __restrict__ Kc, const float* __restrict__ Vc)
{
    extern __shared__ uint32_t sw[];
    uint32_t* Qh = sw + OFF_QH;
    uint32_t* Ql = sw + OFF_QL;
    uint32_t* Kh = sw + OFF_KH;
    uint32_t* Kl = sw + OFF_KL;
    uint32_t* Vf = sw + OFF_VF;
    float*    Sc = (float*)(sw + OFF_SC);
    uint32_t* Pf = sw + OFF_PF;
    float*    rm = (float*)(sw + OFF_AUX);
    float*    rl = rm + 32;
    float*    rs = rl + 32;

    int t = threadIdx.x;
    int w = t >> 5, lane = t & 31;
    int g = lane >> 2, tig = lane & 3;
    int sp = blockIdx.x & (NSPLIT - 1), bk = blockIdx.x >> 4;
    const float* Kb = Kc + (size_t)bk * LKV * DH;
    const float* Vb = Vc + (size_t)bk * LKV * DH;

    int qm = (w & 1) * 16;      // m-half
    int kn = (w >> 1) * 16;     // QK col base (16 cols per warp, 2 groups of 8)
    int dB = (w >> 1) * 32;     // PV d base

    // V prefetch coords: per i (0..15): 8 d x 4 spairs per warp-instruction
    int vd_base = (w & 3) * 32 + (lane & 7);
    int vs_base = (w >> 2) * 16 + (lane >> 3);

    // stage Q (pre-scaled by 1/sqrt(D) in rope_reduce)
#pragma unroll
    for (int i = 0; i < 4; i++) {
        int f4 = t + i * 256;
        int row = f4 >> 5, q4 = f4 & 31;
        float4 v = *(const float4*)(g_q + (size_t)(bk * 32 + row) * DH + q4 * 4);
        uint32_t h0, l0, h1, l1;
        split2(v.x, v.y, h0, l0);
        split2(v.z, v.w, h1, l1);
        *(uint2*)&Qh[row * QSTR + q4 * 2] = make_uint2(h0, h1);
        *(uint2*)&Ql[row * QSTR + q4 * 2] = make_uint2(l0, l1);
    }
    if (t < 32) { rm[t] = -INFINITY; rl[t] = 0.f; }

    float o[4][4] = {};
    float4   kreg[8];     // 64 rows x 128 d / 256 thr
    uint32_t vreg[16];    // fp16-packed V pairs

    int s_base = sp * SPLIT_LEN;

    // prologue: prefetch chunk 0
    {
#pragma unroll
        for (int i = 0; i < 8; i++) {
            int f4 = t + i * 256;
            int row = f4 >> 5, q4 = f4 & 31;
            kreg[i] = *(const float4*)(Kb + (size_t)(s_base + row) * DH + q4 * 4);
        }
#pragma unroll
        for (int i = 0; i < 16; i++) {
            int d = vd_base + (i & 3) * 8;
            int spair = vs_base + (i >> 2) * 4;
            float va = Vb[(size_t)(s_base + 2 * spair) * DH + d];
            float vb = Vb[(size_t)(s_base + 2 * spair + 1) * DH + d];
            vreg[i] = cvt_f16x2(va, vb);
        }
    }

    for (int ch = 0; ch < NCH; ch++) {
        int sc0 = s_base + ch * CS;
        __syncthreads();   // prev PV done; smem K/V free (covers Q staging on first iter)

        // STS current chunk from registers (conflict-free)
#pragma unroll
        for (int i = 0; i < 8; i++) {
            int f4 = t + i * 256;
            int row = f4 >> 5, q4 = f4 & 31;
            uint32_t h0, l0, h1, l1;
            split2(kreg[i].x, kreg[i].y, h0, l0);
            split2(kreg[i].z, kreg[i].w, h1, l1);
            *(uint2*)&Kh[row * QSTR + q4 * 2] = make_uint2(h0, h1);
            *(uint2*)&Kl[row * QSTR + q4 * 2] = make_uint2(l0, l1);
        }
#pragma unroll
        for (int i = 0; i < 16; i++) {
            int d = vd_base + (i & 3) * 8;
            int spair = vs_base + (i >> 2) * 4;
            Vf[d * VSTR + spair] = vreg[i];
        }
        __syncthreads();

        // prefetch next chunk (consumed next iteration -> latency hidden)
        if (ch + 1 < NCH) {
            int sn = sc0 + CS;
#pragma unroll
            for (int i = 0; i < 8; i++) {
                int f4 = t + i * 256;
                int row = f4 >> 5, q4 = f4 & 31;
                kreg[i] = *(const float4*)(Kb + (size_t)(sn + row) * DH + q4 * 4);
            }
#pragma unroll
            for (int i = 0; i < 16; i++) {
                int d = vd_base + (i & 3) * 8;
                int spair = vs_base + (i >> 2) * 4;
                float va = Vb[(size_t)(sn + 2 * spair) * DH + d];
                float vb = Vb[(size_t)(sn + 2 * spair + 1) * DH + d];
                vreg[i] = cvt_f16x2(va, vb);
            }
        }

        // QK^T: warp computes 16 q-rows x 16 s-cols (one Q frag, 2 K groups)
        float sA[4] = {0.f, 0.f, 0.f, 0.f};
        float sB[4] = {0.f, 0.f, 0.f, 0.f};
#pragma unroll
        for (int ksd = 0; ksd < 8; ksd++) {
            int base = ksd * 8;
            uint32_t ah0 = Qh[(qm + g) * QSTR + base + tig];
            uint32_t ah1 = Qh[(qm + g + 8) * QSTR + base + tig];
            uint32_t ah2 = Qh[(qm + g) * QSTR + base + tig + 4];
            uint32_t ah3 = Qh[(qm + g + 8) * QSTR + base + tig + 4];
            uint32_t al0 = Ql[(qm + g) * QSTR + base + tig];
            uint32_t al1 = Ql[(qm + g + 8) * QSTR + base + tig];
            uint32_t al2 = Ql[(qm + g) * QSTR + base + tig + 4];
            uint32_t al3 = Ql[(qm + g + 8) * QSTR + base + tig + 4];
            {
                int srow = kn + g;
                uint32_t bh0 = Kh[srow * QSTR + base + tig];
                uint32_t bh1 = Kh[srow * QSTR + base + tig + 4];
                uint32_t bl0 = Kl[srow * QSTR + base + tig];
                uint32_t bl1 = Kl[srow * QSTR + base + tig + 4];
                mma_bf16(sA, ah0, ah1, ah2, ah3, bh0, bh1);
                mma_bf16(sA, ah0, ah1, ah2, ah3, bl0, bl1);
                mma_bf16(sA, al0, al1, al2, al3, bh0, bh1);
            }
            {
                int srow = kn + 8 + g;
                uint32_t bh0 = Kh[srow * QSTR + base + tig];
                uint32_t bh1 = Kh[srow * QSTR + base + tig + 4];
                uint32_t bl0 = Kl[srow * QSTR + base + tig];
                uint32_t bl1 = Kl[srow * QSTR + base + tig + 4];
                mma_bf16(sB, ah0, ah1, ah2, ah3, bh0, bh1);
                mma_bf16(sB, ah0, ah1, ah2, ah3, bl0, bl1);
                mma_bf16(sB, al0, al1, al2, al3, bh0, bh1);
            }
        }
        {
            int r0 = qm + g, r1 = qm + g + 8;
            int colA = kn + tig * 2;
            int colB = kn + 8 + tig * 2;
            int sgA0 = sc0 + colA, sgA1 = sgA0 + 1;
            int sgB0 = sc0 + colB, sgB1 = sgB0 + 1;
            float a00 = sA[0], a01 = sA[1], a10 = sA[2], a11 = sA[3];
            float b00 = sB[0], b01 = sB[1], b10 = sB[2], b11 = sB[3];
            if (sgA0 > 4088 + (r0 & 7)) a00 = -10000.f;
            if (sgA1 > 4088 + (r0 & 7)) a01 = -10000.f;
            if (sgA0 > 4088 + (r1 & 7)) a10 = -10000.f;
            if (sgA1 > 4088 + (r1 & 7)) a11 = -10000.f;
            if (sgB0 > 4088 + (r0 & 7)) b00 = -10000.f;
            if (sgB1 > 4088 + (r0 & 7)) b01 = -10000.f;
            if (sgB0 > 4088 + (r1 & 7)) b10 = -10000.f;
            if (sgB1 > 4088 + (r1 & 7)) b11 = -10000.f;
            Sc[r0 * SSTR + colA] = a00; Sc[r0 * SSTR + colA + 1] = a01;
            Sc[r1 * SSTR + colA] = a10; Sc[r1 * SSTR + colA + 1] = a11;
            Sc[r0 * SSTR + colB] = b00; Sc[r0 * SSTR + colB + 1] = b01;
            Sc[r1 * SSTR + colB] = b10; Sc[r1 * SSTR + colB + 1] = b11;
        }
        __syncthreads();

        // online softmax: warp w owns rows w*4 .. w*4+3 (64 cols each)
#pragma unroll
        for (int k2 = 0; k2 < 4; k2++) {
            int rr = w * 4 + k2;
            float v0 = Sc[rr * SSTR + lane];
            float v1 = Sc[rr * SSTR + 32 + lane];
            float mx = fmaxf(v0, v1);
#pragma unroll
            for (int off = 16; off > 0; off >>= 1)
                mx = fmaxf(mx, __shfl_xor_sync(0xffffffffu, mx, off));
            float mprev = rm[rr];
            float mnew = fmaxf(mprev, mx);
            float p0 = __expf(v0 - mnew);
            float p1 = __expf(v1 - mnew);
            float ls = p0 + p1;
#pragma unroll
            for (int off = 16; off > 0; off >>= 1)
                ls += __shfl_xor_sync(0xffffffffu, ls, off);
            // pack pairs (2j, 2j+1): j<16 from p0 lanes 2j,2j+1; j>=16 from p1
            float t0 = __shfl_sync(0xffffffffu, p0, (2 * lane) & 31);
            float t1 = __shfl_sync(0xffffffffu, p1, (2 * lane) & 31);
            float u0 = __shfl_sync(0xffffffffu, p0, (2 * lane + 1) & 31);
            float u1 = __shfl_sync(0xffffffffu, p1, (2 * lane + 1) & 31);
            float pe = (lane < 16) ? t0 : t1;
            float po = (lane < 16) ? u0 : u1;
            Pf[rr * PSTR + lane] = cvt_f16x2(pe, po);
            if (lane == 0) {
                float f = __expf(mprev - mnew);
                rl[rr] = rl[rr] * f + ls;
                rm[rr] = mnew;
                rs[rr] = f;
            }
        }
        __syncthreads();

        // rescale + PV (fp16): warp computes 16 q-rows x 32 d-cols, k=64
        float f0 = rs[qm + g], f1 = rs[qm + g + 8];
#pragma unroll
        for (int nt = 0; nt < 4; nt++) {
            o[nt][0] *= f0; o[nt][1] *= f0;
            o[nt][2] *= f1; o[nt][3] *= f1;
        }
#pragma unroll
        for (int kstep = 0; kstep < 4; kstep++) {
            int base = kstep * 8;
            uint32_t p0 = Pf[(qm + g) * PSTR + base + tig];
            uint32_t p1 = Pf[(qm + g + 8) * PSTR + base + tig];
            uint32_t p2 = Pf[(qm + g) * PSTR + base + tig + 4];
            uint32_t p3 = Pf[(qm + g + 8) * PSTR + base + tig + 4];
#pragma unroll
            for (int nt = 0; nt < 4; nt++) {
                int drow = dB + nt * 8 + g;
                uint32_t b0 = Vf[drow * VSTR + base + tig];
                uint32_t b1 = Vf[drow * VSTR + base + tig + 4];
                mma_f16(o[nt], p0, p1, p2, p3, b0, b1);
            }
        }
    }

    int pbase = (bk * NSPLIT + sp) * 32;
    if (t < 32) { g_pm[pbase + t] = rm[t]; g_pl[pbase + t] = rl[t]; }
#pragma unroll
    for (int nt = 0; nt < 4; nt++) {
        int col = dB + nt * 8 + tig * 2;
        int r0 = qm + g, r1 = qm + g + 8;
        g_po[(size_t)(pbase + r0) * DH + col]     = o[nt][0];
        g_po[(size_t)(pbase + r0) * DH + col + 1] = o[nt][1];
        g_po[(size_t)(pbase + r1) * DH + col]     = o[nt][2];
        g_po[(size_t)(pbase + r1) * DH + col + 1] = o[nt][3];
    }
}

// ---------------------------------------------------------------------------
// Merge split partials (log-sum-exp) + relayout to [(b,qq)][h*128+d]
// ---------------------------------------------------------------------------
__global__ void merge_kernel() {
    int i = blockIdx.x * 256 + threadIdx.x;   // 0 .. 262143
    int d = i & 127;
    int rg = i >> 7;
    int bk = rg >> 5, r = rg & 31;
    float mv[NSPLIT];
    float mmax = -INFINITY;
#pragma unroll
    for (int sp = 0; sp < NSPLIT; sp++) {
        mv[sp] = g_pm[(bk * NSPLIT + sp) * 32 + r];
        mmax = fmaxf(mmax, mv[sp]);
    }
    float num = 0.f, den = 0.f;
#pragma unroll
    for (int sp = 0; sp < NSPLIT; sp++) {
        float wgt = __expf(mv[sp] - mmax);
        num += wgt * g_po[(size_t)((bk * NSPLIT + sp) * 32 + r) * DH + d];
        den += wgt * g_pl[(bk * NSPLIT + sp) * 32 + r];
    }
    float val = num / den;
    int b = bk >> 3, kvh = bk & 7, gg = r >> 3, qq = r & 7;
    int h = kvh * NG + gg;
    g_attn[(b * NQ + qq) * HID + h * DH + d] = val;
}

// ---------------------------------------------------------------------------
// kernel_launch
// ---------------------------------------------------------------------------
extern "C" void kernel_launch(void* const* d_in, const int* in_sizes, int n_in,
                              void* d_out, int out_size) {
    (void)in_sizes; (void)n_in; (void)out_size;
    const float* hidden = (const float*)d_in[0];
    const int* pos = (const int*)d_in[1];
    const float* kc = (const float*)d_in[2];
    const float* vc = (const float*)d_in[3];
    const float* qw = (const float*)d_in[5];
    const float* ow = (const float*)d_in[6];
    float* out = (float*)d_out;

    static int attr_done = 0;
    if (!attr_done) {
        cudaFuncSetAttribute(attn_mma_kernel,
                             cudaFuncAttributeMaxDynamicSharedMemorySize,
                             SMEM_WORDS * 4);
        attr_done = 1;
    }

    rope_setup_kernel<<<1, 256>>>(pos);
    gemm_mma_kernel<<<dim3(HID / 64, KSPLIT), 256>>>(hidden, qw);
    rope_reduce_kernel<<<512, 256>>>();
    attn_mma_kernel<<<64 * NSPLIT, 256, SMEM_WORDS * 4>>>(kc, vc);
    merge_kernel<<<1024, 256>>>();
    gemm_f16_kernel<<<dim3(HID / 64, KSPLIT), 256>>>(ow);
    reduce_out_kernel<<<1024, 256>>>(out);
}